// round 8
// baseline (speedup 1.0000x reference)
#include <cuda_runtime.h>
#include <math.h>
#include <stdint.h>

#define S   1024
#define H   2048
#define NH  16
#define HD  128
#define E   16
#define TOPK 4
#define IM  1408
#define IS  5632
#define EPS 1e-6f

// ---------------- scratch (device globals) ----------------
__device__ float g_h1[S*H];
__device__ float g_q[S*H];
__device__ float g_k[S*H];
__device__ float g_v[S*H];
__device__ float g_attn[S*H];
__device__ float g_x2[S*H];
__device__ float g_h2[S*H];
__device__ float g_gs[S*IS];
__device__ float g_us[S*IS];
__device__ float g_shared[S*H];
__device__ float g_logits[S*E];
__device__ float g_sg[S];
__device__ int   g_cnt[E];
__device__ int   g_tk_e[S*TOPK];
__device__ int   g_tk_slot[S*TOPK];
__device__ float g_tk_w[S*TOPK];
__device__ int   g_tok[E*S];
__device__ float g_gbuf[E*S*IM];
__device__ float g_ubuf[E*S*IM];
__device__ float g_ybuf[E*S*H];
__device__ float g_part[4194304];

// ---------------- block reductions ----------------
__device__ __forceinline__ float blockReduceSum(float v) {
    __shared__ float sh[33];
    int lane = threadIdx.x & 31, wid = threadIdx.x >> 5;
    #pragma unroll
    for (int o = 16; o; o >>= 1) v += __shfl_down_sync(0xffffffffu, v, o);
    if (lane == 0) sh[wid] = v;
    __syncthreads();
    int nw = (blockDim.x + 31) >> 5;
    float t = (threadIdx.x < nw) ? sh[threadIdx.x] : 0.f;
    if (wid == 0) {
        #pragma unroll
        for (int o = 16; o; o >>= 1) t += __shfl_down_sync(0xffffffffu, t, o);
        if (lane == 0) sh[32] = t;
    }
    __syncthreads();
    float r = sh[32];
    __syncthreads();
    return r;
}

// ---------------- tf32 helpers ----------------
__device__ __forceinline__ uint32_t f2tf32(float f) {
    uint32_t r;
    asm("cvt.rna.tf32.f32 %0, %1;" : "=r"(r) : "f"(f));
    return r;
}

__device__ __forceinline__ void mma_tf32(float& d0, float& d1, float& d2, float& d3,
                                         uint32_t a0, uint32_t a1, uint32_t a2, uint32_t a3,
                                         uint32_t b0, uint32_t b1) {
    asm volatile(
        "mma.sync.aligned.m16n8k8.row.col.f32.tf32.tf32.f32 "
        "{%0,%1,%2,%3}, {%4,%5,%6,%7}, {%8,%9}, {%0,%1,%2,%3};"
        : "+f"(d0), "+f"(d1), "+f"(d2), "+f"(d3)
        : "r"(a0), "r"(a1), "r"(a2), "r"(a3), "r"(b0), "r"(b1));
}

__device__ __forceinline__ void cp_async16(uint32_t smem_addr, const void* gptr) {
    asm volatile("cp.async.cg.shared.global [%0], [%1], 16;"
                 :: "r"(smem_addr), "l"(gptr));
}
__device__ __forceinline__ void cp_commit() {
    asm volatile("cp.async.commit_group;" ::: "memory");
}
__device__ __forceinline__ void cp_wait0() {
    asm volatile("cp.async.wait_group 0;" ::: "memory");
}

// ---------------- TF32 GEMM: BK=32, 128 threads, 64x64 warp tiles ----------------
#define LDA_SH 36                 // [128][32] m-major tiles, pad to 36
#define LDB_SH 136                // [32][128] k-major B, pad to 136
#define TG_STG 4608               // max(128*36, 32*136+pad) per stage
#define TG_SMEM (4 * TG_STG * 4)  // 2 stages x (A,B) in bytes = 73728

struct GSet { const float* B; float* C; const float* bias; };
struct GSets { GSet s[3]; };

__global__ void __launch_bounds__(128, 2)
tgemm_kernel(const float* __restrict__ A, GSets sets,
             int M, int N, int K, int lda, int ldb, int ldc,
             long long sA, long long sB, long long sC,
             float alpha, int transB, const int* __restrict__ mcnt,
             int inner, int nsplit, int ksz,
             float* __restrict__ part, long long sSplit,
             const int* __restrict__ rowidx_all)
{
    extern __shared__ uint32_t dsm[];
    uint32_t* Ast[2] = { dsm,              dsm + TG_STG };
    uint32_t* Bst[2] = { dsm + 2 * TG_STG, dsm + 3 * TG_STG };

    const int z = blockIdx.z;
    const int sp  = z % nsplit;
    const int t   = z / nsplit;
    const int ib  = t % inner;
    const int set = t / inner;

    const int Mfull = M;
    if (mcnt) M = mcnt[ib];
    const int m0 = blockIdx.y * 128;
    if (m0 >= M) return;
    const int n0 = blockIdx.x * 128;

    const float* Ab = A + (long long)ib * sA;
    const float* Bb = sets.s[set].B + (long long)ib * sB;
    const float* bias = sets.s[set].bias;
    const int* rowidx = rowidx_all ? rowidx_all + (long long)ib * S : nullptr;
    float* Cb;
    int ldcc;
    if (nsplit > 1) {
        Cb = part + (long long)sp * sSplit + (long long)ib * ((long long)Mfull * N);
        ldcc = N;
        bias = nullptr;
    } else {
        Cb = sets.s[set].C + (long long)ib * sC;
        ldcc = ldc;
    }

    const int kbeg = (nsplit > 1) ? sp * ksz : 0;
    const int kend = (nsplit > 1) ? kbeg + ksz : K;

    const int tid  = threadIdx.x;
    const int lane = tid & 31;
    const int warp = tid >> 5;          // 0..3
    const int wm   = (warp & 1) * 64;   // 2x2 warp grid of 64x64 tiles
    const int wn   = (warp >> 1) * 64;
    const int g    = lane >> 2;
    const int tg   = lane & 3;

    // gmem<->smem mapping (BK=32)
    const int a_r  = tid >> 3;          // 0..15 (+16q)
    const int a_kq = (tid & 7) * 4;     // 0..28
    const int b_kr = tid >> 5;          // 0..3  (+4q)
    const int b_n4 = (tid & 31) * 4;

    // loop-invariant row offsets (incl. rowidx, resolved once); -1 = out of range
    int aOff[8];
    #pragma unroll
    for (int q = 0; q < 8; q++) {
        int r = m0 + a_r + 16 * q;
        aOff[q] = (r < M) ? (rowidx ? rowidx[r] : r) : -1;
    }
    int bOff[8];
    const float* bCol = nullptr;
    if (!transB) {
        if (n0 + b_n4 < N) bCol = Bb + n0 + b_n4;
        #pragma unroll
        for (int q = 0; q < 8; q++) bOff[q] = 0;
    } else {
        #pragma unroll
        for (int q = 0; q < 8; q++) {
            int r = n0 + a_r + 16 * q;
            bOff[q] = (r < N) ? r : -1;
        }
    }

    float acc[4][8][4];
    #pragma unroll
    for (int i = 0; i < 4; i++)
        #pragma unroll
        for (int j = 0; j < 8; j++)
            #pragma unroll
            for (int c = 0; c < 4; c++) acc[i][j][c] = 0.f;

    float4 avr[4], bvr[4];
    const float4 zf4 = make_float4(0.f, 0.f, 0.f, 0.f);

    // half h covers quads q = 4h..4h+3 of the next tile at base k = ktn
    auto load_half = [&](int h, int ktn) {
        #pragma unroll
        for (int j = 0; j < 4; j++) {
            int q = 4 * h + j;
            avr[j] = (aOff[q] >= 0)
                ? *reinterpret_cast<const float4*>(Ab + (long long)aOff[q] * lda + ktn + a_kq)
                : zf4;
            if (!transB) {
                bvr[j] = bCol
                    ? *reinterpret_cast<const float4*>(bCol + (long long)(ktn + b_kr + 4 * q) * ldb)
                    : zf4;
            } else {
                bvr[j] = (bOff[q] >= 0)
                    ? *reinterpret_cast<const float4*>(Bb + (long long)bOff[q] * ldb + ktn + a_kq)
                    : zf4;
            }
        }
    };
    auto store_half = [&](int h, uint32_t* Asn, uint32_t* Bsn) {
        #pragma unroll
        for (int j = 0; j < 4; j++) {
            int q = 4 * h + j;
            int r = a_r + 16 * q;
            uint4 va = make_uint4(f2tf32(avr[j].x), f2tf32(avr[j].y),
                                  f2tf32(avr[j].z), f2tf32(avr[j].w));
            *reinterpret_cast<uint4*>(&Asn[r * LDA_SH + a_kq]) = va;
            uint4 vb = make_uint4(f2tf32(bvr[j].x), f2tf32(bvr[j].y),
                                  f2tf32(bvr[j].z), f2tf32(bvr[j].w));
            if (!transB) {
                int k = b_kr + 4 * q;
                *reinterpret_cast<uint4*>(&Bsn[k * LDB_SH + b_n4]) = vb;
            } else {
                *reinterpret_cast<uint4*>(&Bsn[r * LDA_SH + a_kq]) = vb;
            }
        }
    };
    auto do_k8 = [&](const uint32_t* Asp, const uint32_t* Bsp, int kk) {
        uint32_t af[4][4];
        #pragma unroll
        for (int mt = 0; mt < 4; mt++) {
            const uint32_t* base = &Asp[(wm + mt * 16 + g) * LDA_SH + kk + tg];
            af[mt][0] = base[0];
            af[mt][1] = base[8 * LDA_SH];
            af[mt][2] = base[4];
            af[mt][3] = base[8 * LDA_SH + 4];
        }
        uint32_t bf[8][2];
        if (!transB) {
            #pragma unroll
            for (int nt = 0; nt < 8; nt++) {
                int n = wn + nt * 8 + g;
                bf[nt][0] = Bsp[(kk + tg) * LDB_SH + n];
                bf[nt][1] = Bsp[(kk + tg + 4) * LDB_SH + n];
            }
        } else {
            #pragma unroll
            for (int nt = 0; nt < 8; nt++) {
                int n = wn + nt * 8 + g;
                bf[nt][0] = Bsp[n * LDA_SH + kk + tg];
                bf[nt][1] = Bsp[n * LDA_SH + kk + tg + 4];
            }
        }
        #pragma unroll
        for (int mt = 0; mt < 4; mt++)
            #pragma unroll
            for (int nt = 0; nt < 8; nt++)
                mma_tf32(acc[mt][nt][0], acc[mt][nt][1], acc[mt][nt][2], acc[mt][nt][3],
                         af[mt][0], af[mt][1], af[mt][2], af[mt][3],
                         bf[nt][0], bf[nt][1]);
    };

    // prologue: fill stage 0 (both halves)
    load_half(0, kbeg);  store_half(0, Ast[0], Bst[0]);
    load_half(1, kbeg);  store_half(1, Ast[0], Bst[0]);
    __syncthreads();

    int p = 0;
    for (int kt = kbeg; kt < kend; kt += 32) {
        const bool has_next = (kt + 32 < kend);
        const uint32_t* Asp = Ast[p];
        const uint32_t* Bsp = Bst[p];
        uint32_t* Asn = Ast[p ^ 1];
        uint32_t* Bsn = Bst[p ^ 1];

        if (has_next) load_half(0, kt + 32);
        do_k8(Asp, Bsp, 0);
        do_k8(Asp, Bsp, 8);
        if (has_next) {
            store_half(0, Asn, Bsn);
            load_half(1, kt + 32);
        }
        do_k8(Asp, Bsp, 16);
        do_k8(Asp, Bsp, 24);
        if (has_next) {
            store_half(1, Asn, Bsn);
            __syncthreads();
            p ^= 1;
        }
    }

    // epilogue
    #pragma unroll
    for (int mt = 0; mt < 4; mt++) {
        int r0 = m0 + wm + mt * 16 + g;
        int r1 = r0 + 8;
        #pragma unroll
        for (int nt = 0; nt < 8; nt++) {
            int col = n0 + wn + nt * 8 + 2 * tg;
            if (col >= N) continue;
            float b0 = bias ? bias[col]     : 0.f;
            float b1 = bias ? bias[col + 1] : 0.f;
            if (r0 < M) {
                float2 v = make_float2(acc[mt][nt][0] * alpha + b0,
                                       acc[mt][nt][1] * alpha + b1);
                *reinterpret_cast<float2*>(&Cb[(long long)r0 * ldcc + col]) = v;
            }
            if (r1 < M) {
                float2 v = make_float2(acc[mt][nt][2] * alpha + b0,
                                       acc[mt][nt][3] * alpha + b1);
                *reinterpret_cast<float2*>(&Cb[(long long)r1 * ldcc + col]) = v;
            }
        }
    }
}

// linear float4 split-K reduce
__global__ void reduce_split_kernel(const float4* __restrict__ P, float4* __restrict__ C,
                                    const float4* __restrict__ addend,
                                    int nsplit, long long sSplit4, long long total4)
{
    long long i = (long long)blockIdx.x * blockDim.x + threadIdx.x;
    if (i >= total4) return;
    float4 s = P[i];
    for (int sp = 1; sp < nsplit; sp++) {
        float4 t = P[sp * sSplit4 + i];
        s.x += t.x; s.y += t.y; s.z += t.z; s.w += t.w;
    }
    if (addend) {
        float4 t = addend[i];
        s.x += t.x; s.y += t.y; s.z += t.z; s.w += t.w;
    }
    C[i] = s;
}

// ---------------- flash attention v2 (unchanged) ----------------
#define FAQ_LD 132
#define FAK_LD 132
#define FAV_LD 136
#define FAP_LD 36
#define FA_QS   0
#define FA_KV0  (64*FAQ_LD)
#define FA_KVST (32*FAK_LD + 32*FAV_LD)
#define FA_PS   (FA_KV0 + 2*FA_KVST)
#define FA_TOT  (FA_PS + 4*16*FAP_LD)
#define ATTN_SCALE 0.08838834764831845f

__global__ void __launch_bounds__(128)
flash_attn_kernel(const float* __restrict__ Q, const float* __restrict__ K,
                  const float* __restrict__ V, float* __restrict__ O)
{
    extern __shared__ uint32_t sh[];
    const int qb   = (gridDim.x - 1) - blockIdx.x;
    const int hh   = blockIdx.y;
    const int tid  = threadIdx.x;
    const int lane = tid & 31;
    const int warp = tid >> 5;
    const int g    = lane >> 2;
    const int tg   = lane & 3;
    const int wm   = warp * 16;
    const int q0   = qb * 64;
    const long long hoff = (long long)hh * HD;

    const uint32_t shbase = (uint32_t)__cvta_generic_to_shared(sh);

    #pragma unroll
    for (int j = 0; j < 16; j++) {
        int idx = tid + 128 * j;
        int r = idx >> 5, c4 = (idx & 31) * 4;
        float4 t = *reinterpret_cast<const float4*>(&Q[(long long)(q0 + r) * H + hoff + c4]);
        uint4 v = make_uint4(f2tf32(t.x * ATTN_SCALE), f2tf32(t.y * ATTN_SCALE),
                             f2tf32(t.z * ATTN_SCALE), f2tf32(t.w * ATTN_SCALE));
        *reinterpret_cast<uint4*>(&sh[FA_QS + r * FAQ_LD + c4]) = v;
    }

    const int ldrow = tid >> 5;
    const int ldc4  = (tid & 31) * 4;

    auto issue_chunk = [&](int c, int s) {
        uint32_t kbase = shbase + (FA_KV0 + s * FA_KVST) * 4;
        uint32_t vbase = kbase + 32 * FAK_LD * 4;
        #pragma unroll
        for (int j = 0; j < 8; j++) {
            int r = ldrow + 4 * j;
            long long gofs = (long long)(c * 32 + r) * H + hoff + ldc4;
            cp_async16(kbase + (r * FAK_LD + ldc4) * 4, &K[gofs]);
            cp_async16(vbase + (r * FAV_LD + ldc4) * 4, &V[gofs]);
        }
        cp_commit();
    };

    float Oacc[16][4];
    #pragma unroll
    for (int nt = 0; nt < 16; nt++)
        #pragma unroll
        for (int c = 0; c < 4; c++) Oacc[nt][c] = 0.f;
    float m0r = -1e30f, m1r = -1e30f, l0r = 0.f, l1r = 0.f;

    uint32_t* Pw = &sh[FA_PS + warp * 16 * FAP_LD];
    const int nc = 2 * qb + 2;

    issue_chunk(0, 0);

    for (int c = 0; c < nc; c++) {
        cp_wait0();
        __syncthreads();
        if (c + 1 < nc) issue_chunk(c + 1, (c + 1) & 1);

        const uint32_t* K_ = &sh[FA_KV0 + (c & 1) * FA_KVST];
        const uint32_t* V_ = K_ + 32 * FAK_LD;

        float Sacc[4][4];
        #pragma unroll
        for (int nt = 0; nt < 4; nt++)
            #pragma unroll
            for (int cc = 0; cc < 4; cc++) Sacc[nt][cc] = 0.f;

        #pragma unroll
        for (int kk = 0; kk < 128; kk += 8) {
            uint32_t a0 = sh[FA_QS + (wm + g) * FAQ_LD + kk + tg];
            uint32_t a1 = sh[FA_QS + (wm + g + 8) * FAQ_LD + kk + tg];
            uint32_t a2 = sh[FA_QS + (wm + g) * FAQ_LD + kk + tg + 4];
            uint32_t a3 = sh[FA_QS + (wm + g + 8) * FAQ_LD + kk + tg + 4];
            #pragma unroll
            for (int nt = 0; nt < 4; nt++) {
                uint32_t b0 = K_[(nt * 8 + g) * FAK_LD + kk + tg];
                uint32_t b1 = K_[(nt * 8 + g) * FAK_LD + kk + tg + 4];
                mma_tf32(Sacc[nt][0], Sacc[nt][1], Sacc[nt][2], Sacc[nt][3],
                         a0, a1, a2, a3, b0, b1);
            }
        }

        if (c >= 2 * qb) {
            int r0g = q0 + wm + g, r1g = r0g + 8;
            #pragma unroll
            for (int nt = 0; nt < 4; nt++) {
                int c0 = c * 32 + nt * 8 + 2 * tg, c1 = c0 + 1;
                if (c0 > r0g) Sacc[nt][0] = -1e30f;
                if (c1 > r0g) Sacc[nt][1] = -1e30f;
                if (c0 > r1g) Sacc[nt][2] = -1e30f;
                if (c1 > r1g) Sacc[nt][3] = -1e30f;
            }
        }

        float rmax0 = -1e30f, rmax1 = -1e30f;
        #pragma unroll
        for (int nt = 0; nt < 4; nt++) {
            rmax0 = fmaxf(rmax0, fmaxf(Sacc[nt][0], Sacc[nt][1]));
            rmax1 = fmaxf(rmax1, fmaxf(Sacc[nt][2], Sacc[nt][3]));
        }
        rmax0 = fmaxf(rmax0, __shfl_xor_sync(0xffffffffu, rmax0, 1));
        rmax0 = fmaxf(rmax0, __shfl_xor_sync(0xffffffffu, rmax0, 2));
        rmax1 = fmaxf(rmax1, __shfl_xor_sync(0xffffffffu, rmax1, 1));
        rmax1 = fmaxf(rmax1, __shfl_xor_sync(0xffffffffu, rmax1, 2));

        float nm0 = fmaxf(m0r, rmax0), nm1 = fmaxf(m1r, rmax1);
        float al0 = __expf(m0r - nm0), al1 = __expf(m1r - nm1);
        float sum0 = 0.f, sum1 = 0.f;
        #pragma unroll
        for (int nt = 0; nt < 4; nt++) {
            float p00 = __expf(Sacc[nt][0] - nm0);
            float p01 = __expf(Sacc[nt][1] - nm0);
            float p10 = __expf(Sacc[nt][2] - nm1);
            float p11 = __expf(Sacc[nt][3] - nm1);
            sum0 += p00 + p01; sum1 += p10 + p11;
            int cl = nt * 8 + 2 * tg;
            Pw[g * FAP_LD + cl]           = f2tf32(p00);
            Pw[g * FAP_LD + cl + 1]       = f2tf32(p01);
            Pw[(g + 8) * FAP_LD + cl]     = f2tf32(p10);
            Pw[(g + 8) * FAP_LD + cl + 1] = f2tf32(p11);
        }
        sum0 += __shfl_xor_sync(0xffffffffu, sum0, 1);
        sum0 += __shfl_xor_sync(0xffffffffu, sum0, 2);
        sum1 += __shfl_xor_sync(0xffffffffu, sum1, 1);
        sum1 += __shfl_xor_sync(0xffffffffu, sum1, 2);
        l0r = l0r * al0 + sum0;
        l1r = l1r * al1 + sum1;
        m0r = nm0; m1r = nm1;

        #pragma unroll
        for (int nt = 0; nt < 16; nt++) {
            Oacc[nt][0] *= al0; Oacc[nt][1] *= al0;
            Oacc[nt][2] *= al1; Oacc[nt][3] *= al1;
        }

        __syncwarp();

        #pragma unroll
        for (int kk = 0; kk < 32; kk += 8) {
            uint32_t a0 = Pw[g * FAP_LD + kk + tg];
            uint32_t a1 = Pw[(g + 8) * FAP_LD + kk + tg];
            uint32_t a2 = Pw[g * FAP_LD + kk + tg + 4];
            uint32_t a3 = Pw[(g + 8) * FAP_LD + kk + tg + 4];
            #pragma unroll
            for (int nt = 0; nt < 16; nt++) {
                uint32_t b0 = V_[(kk + tg) * FAV_LD + nt * 8 + g];
                uint32_t b1 = V_[(kk + tg + 4) * FAV_LD + nt * 8 + g];
                mma_tf32(Oacc[nt][0], Oacc[nt][1], Oacc[nt][2], Oacc[nt][3],
                         a0, a1, a2, a3, b0, b1);
            }
        }
    }

    float inv0 = 1.f / l0r, inv1 = 1.f / l1r;
    long long r0 = q0 + wm + g, r1 = r0 + 8;
    #pragma unroll
    for (int nt = 0; nt < 16; nt++) {
        int c = nt * 8 + 2 * tg;
        *reinterpret_cast<float2*>(&O[r0 * H + hoff + c]) =
            make_float2(Oacc[nt][0] * inv0, Oacc[nt][1] * inv0);
        *reinterpret_cast<float2*>(&O[r1 * H + hoff + c]) =
            make_float2(Oacc[nt][2] * inv1, Oacc[nt][3] * inv1);
    }
}

// ---------------- elementwise / norm ----------------
__global__ void rmsnorm_kernel(const float* __restrict__ x, const float* __restrict__ w,
                               float* __restrict__ y) {
    int t = blockIdx.x;
    const float4* xr = reinterpret_cast<const float4*>(x + (long long)t * H);
    const float4* w4 = reinterpret_cast<const float4*>(w);
    float4* yr = reinterpret_cast<float4*>(y + (long long)t * H);
    float s = 0.f;
    for (int i = threadIdx.x; i < H / 4; i += blockDim.x) {
        float4 v = xr[i];
        s += v.x * v.x + v.y * v.y + v.z * v.z + v.w * v.w;
    }
    s = blockReduceSum(s);
    float scale = rsqrtf(s / (float)H + EPS);
    for (int i = threadIdx.x; i < H / 4; i += blockDim.x) {
        float4 v = xr[i], ww = w4[i];
        yr[i] = make_float4(v.x * scale * ww.x, v.y * scale * ww.y,
                            v.z * scale * ww.z, v.w * scale * ww.w);
    }
}

__global__ void rope_kernel(const int* __restrict__ pos, float* __restrict__ q,
                            float* __restrict__ k) {
    int t = blockIdx.x;
    int h = threadIdx.x >> 6;
    int d = threadIdx.x & 63;
    float p = (float)pos[t];
    float inv = exp2f(-(float)d * 0.31143075889569023f);
    float ang = p * inv;
    float sn, cs;
    sincosf(ang, &sn, &cs);
    long long base = (long long)t * H + h * HD;
    float x1 = q[base + d], x2 = q[base + 64 + d];
    q[base + d]      = x1 * cs - x2 * sn;
    q[base + 64 + d] = x2 * cs + x1 * sn;
    x1 = k[base + d]; x2 = k[base + 64 + d];
    k[base + d]      = x1 * cs - x2 * sn;
    k[base + 64 + d] = x2 * cs + x1 * sn;
}

__global__ void silumul4_kernel(float4* __restrict__ g, const float4* __restrict__ u, int n4) {
    int i = blockIdx.x * blockDim.x + threadIdx.x;
    if (i >= n4) return;
    float4 x = g[i], y = u[i];
    x.x = (x.x / (1.f + __expf(-x.x))) * y.x;
    x.y = (x.y / (1.f + __expf(-x.y))) * y.y;
    x.z = (x.z / (1.f + __expf(-x.z))) * y.z;
    x.w = (x.w / (1.f + __expf(-x.w))) * y.w;
    g[i] = x;
}

__global__ void sgate_kernel(const float* __restrict__ h2, const float* __restrict__ wsg,
                             float* __restrict__ sg) {
    int t = blockIdx.x;
    const float4* xr = reinterpret_cast<const float4*>(h2 + (long long)t * H);
    const float4* w4 = reinterpret_cast<const float4*>(wsg);
    float s = 0.f;
    for (int i = threadIdx.x; i < H / 4; i += blockDim.x) {
        float4 v = xr[i], w = w4[i];
        s += v.x * w.x + v.y * w.y + v.z * w.z + v.w * w.w;
    }
    s = blockReduceSum(s);
    if (threadIdx.x == 0) sg[t] = 1.f / (1.f + __expf(-s));
}

// ---------------- MoE routing ----------------
__global__ void zero_cnt_kernel(int* cnt) { if (threadIdx.x < E) cnt[threadIdx.x] = 0; }

__global__ void routing_kernel(const float* __restrict__ logits, int* __restrict__ cnt,
                               int* __restrict__ tke, int* __restrict__ tks,
                               float* __restrict__ tkw, int* __restrict__ tok) {
    int t = blockIdx.x * blockDim.x + threadIdx.x;
    if (t >= S) return;
    float p[E];
    float mx = -3.4e38f;
    #pragma unroll
    for (int e = 0; e < E; e++) { p[e] = logits[t * E + e]; mx = fmaxf(mx, p[e]); }
    float sum = 0.f;
    #pragma unroll
    for (int e = 0; e < E; e++) { p[e] = __expf(p[e] - mx); sum += p[e]; }
    float inv = 1.f / sum;
    #pragma unroll
    for (int e = 0; e < E; e++) p[e] *= inv;
    int ids[TOPK]; float ws[TOPK]; float wsum = 0.f;
    #pragma unroll
    for (int k = 0; k < TOPK; k++) {
        float bv = -1.f; int bi = 0;
        #pragma unroll
        for (int e = 0; e < E; e++) if (p[e] > bv) { bv = p[e]; bi = e; }
        ids[k] = bi; ws[k] = bv; wsum += bv; p[bi] = -2.f;
    }
    float wi = 1.f / wsum;
    #pragma unroll
    for (int k = 0; k < TOPK; k++) {
        int slot = atomicAdd(&cnt[ids[k]], 1);
        tke[t * TOPK + k] = ids[k];
        tks[t * TOPK + k] = slot;
        tkw[t * TOPK + k] = ws[k] * wi;
        tok[ids[k] * S + slot] = t;
    }
}

__global__ void silumul_expert_kernel(float4* __restrict__ gbuf, const float4* __restrict__ ubuf,
                                      const int* __restrict__ cnt) {
    int e = blockIdx.y, slot = blockIdx.x;
    if (slot >= cnt[e]) return;
    long long base = ((long long)e * S + slot) * (IM / 4);
    for (int i = threadIdx.x; i < IM / 4; i += blockDim.x) {
        float4 x = gbuf[base + i], y = ubuf[base + i];
        x.x = (x.x / (1.f + __expf(-x.x))) * y.x;
        x.y = (x.y / (1.f + __expf(-x.y))) * y.y;
        x.z = (x.z / (1.f + __expf(-x.z))) * y.z;
        x.w = (x.w / (1.f + __expf(-x.w))) * y.w;
        gbuf[base + i] = x;
    }
}

__global__ void combine_kernel(const float* __restrict__ shrd, const float* __restrict__ sg,
                               const float* __restrict__ ybuf,
                               const int* __restrict__ tke, const int* __restrict__ tks,
                               const float* __restrict__ tkw, float* __restrict__ out) {
    int t = blockIdx.x;
    float gg = sg[t];
    int e0 = tke[t*4+0], e1 = tke[t*4+1], e2 = tke[t*4+2], e3 = tke[t*4+3];
    int s0 = tks[t*4+0], s1 = tks[t*4+1], s2 = tks[t*4+2], s3 = tks[t*4+3];
    float w0 = tkw[t*4+0], w1 = tkw[t*4+1], w2 = tkw[t*4+2], w3 = tkw[t*4+3];
    const float4* y0 = reinterpret_cast<const float4*>(ybuf + ((long long)e0 * S + s0) * H);
    const float4* y1 = reinterpret_cast<const float4*>(ybuf + ((long long)e1 * S + s1) * H);
    const float4* y2 = reinterpret_cast<const float4*>(ybuf + ((long long)e2 * S + s2) * H);
    const float4* y3 = reinterpret_cast<const float4*>(ybuf + ((long long)e3 * S + s3) * H);
    const float4* sh4 = reinterpret_cast<const float4*>(shrd + (long long)t * H);
    float4* o = reinterpret_cast<float4*>(out + (long long)t * H);
    for (int i = threadIdx.x; i < H / 4; i += blockDim.x) {
        float4 a = sh4[i], b0 = y0[i], b1 = y1[i], b2 = y2[i], b3 = y3[i];
        o[i] = make_float4(
            gg * a.x + w0 * b0.x + w1 * b1.x + w2 * b2.x + w3 * b3.x,
            gg * a.y + w0 * b0.y + w1 * b1.y + w2 * b2.y + w3 * b3.y,
            gg * a.z + w0 * b0.z + w1 * b1.z + w2 * b2.z + w3 * b3.z,
            gg * a.w + w0 * b0.w + w1 * b1.w + w2 * b2.w + w3 * b3.w);
    }
}

// ---------------- host orchestration ----------------
static inline void gemm_multi(const float* A, const GSets& sets, int nsets,
                              int M, int N, int K, int lda, int ldb, int ldc,
                              long long sA, long long sB, long long sC,
                              float alpha, int transB, const int* mcnt, int inner,
                              int nsplit = 1, int ksz = 0, float* part = nullptr,
                              long long sSplit = 0, const int* rowidx = nullptr) {
    dim3 grid((N + 127) / 128, (M + 127) / 128, nsets * inner * nsplit);
    tgemm_kernel<<<grid, 128, TG_SMEM>>>(A, sets, M, N, K, lda, ldb, ldc, sA, sB, sC,
                                         alpha, transB, mcnt, inner, nsplit, ksz,
                                         part, sSplit, rowidx);
}

static inline void gemm1(const float* A, const float* B, const float* bias, float* C,
                         int M, int N, int K, int lda, int ldb, int ldc,
                         long long sA, long long sB, long long sC,
                         float alpha, int transB, const int* mcnt, int inner) {
    GSets s{}; s.s[0] = {B, C, bias};
    gemm_multi(A, s, 1, M, N, K, lda, ldb, ldc, sA, sB, sC, alpha, transB, mcnt, inner);
}

extern "C" void kernel_launch(void* const* d_in, const int* in_sizes, int n_in,
                              void* d_out, int out_size) {
    const int*   positions = (const int*)  d_in[0];
    const float* hidden    = (const float*)d_in[1];
    const float* ln1       = (const float*)d_in[2];
    const float* ln2       = (const float*)d_in[3];
    const float* q_w       = (const float*)d_in[4];
    const float* q_b       = (const float*)d_in[5];
    const float* k_w       = (const float*)d_in[6];
    const float* k_b       = (const float*)d_in[7];
    const float* v_w       = (const float*)d_in[8];
    const float* v_b       = (const float*)d_in[9];
    const float* o_w       = (const float*)d_in[10];
    const float* router_w  = (const float*)d_in[11];
    const float* we_gate   = (const float*)d_in[12];
    const float* we_up     = (const float*)d_in[13];
    const float* we_down   = (const float*)d_in[14];
    const float* ws_gate   = (const float*)d_in[15];
    const float* ws_up     = (const float*)d_in[16];
    const float* ws_down   = (const float*)d_in[17];
    const float* wsg       = (const float*)d_in[18];
    float* out = (float*)d_out;

    float *h1, *q, *k, *v, *attn, *x2, *h2, *gs, *us, *shrd;
    float *logits, *sgv, *gbuf, *ubuf, *ybuf, *tkw, *part;
    int *cnt, *tke, *tks, *tok;
    cudaGetSymbolAddress((void**)&h1,     g_h1);
    cudaGetSymbolAddress((void**)&q,      g_q);
    cudaGetSymbolAddress((void**)&k,      g_k);
    cudaGetSymbolAddress((void**)&v,      g_v);
    cudaGetSymbolAddress((void**)&attn,   g_attn);
    cudaGetSymbolAddress((void**)&x2,     g_x2);
    cudaGetSymbolAddress((void**)&h2,     g_h2);
    cudaGetSymbolAddress((void**)&gs,     g_gs);
    cudaGetSymbolAddress((void**)&us,     g_us);
    cudaGetSymbolAddress((void**)&shrd,   g_shared);
    cudaGetSymbolAddress((void**)&logits, g_logits);
    cudaGetSymbolAddress((void**)&sgv,    g_sg);
    cudaGetSymbolAddress((void**)&cnt,    g_cnt);
    cudaGetSymbolAddress((void**)&tke,    g_tk_e);
    cudaGetSymbolAddress((void**)&tks,    g_tk_slot);
    cudaGetSymbolAddress((void**)&tkw,    g_tk_w);
    cudaGetSymbolAddress((void**)&tok,    g_tok);
    cudaGetSymbolAddress((void**)&gbuf,   g_gbuf);
    cudaGetSymbolAddress((void**)&ubuf,   g_ubuf);
    cudaGetSymbolAddress((void**)&ybuf,   g_ybuf);
    cudaGetSymbolAddress((void**)&part,   g_part);

    cudaFuncSetAttribute(flash_attn_kernel,
                         cudaFuncAttributeMaxDynamicSharedMemorySize, FA_TOT * 4);
    cudaFuncSetAttribute(tgemm_kernel,
                         cudaFuncAttributeMaxDynamicSharedMemorySize, TG_SMEM);

    // --- pre-attention norm + fused QKV + RoPE ---
    rmsnorm_kernel<<<S, 256>>>(hidden, ln1, h1);
    {
        GSets s{};
        s.s[0] = {q_w, q, q_b};
        s.s[1] = {k_w, k, k_b};
        s.s[2] = {v_w, v, v_b};
        gemm_multi(h1, s, 3, S, H, H, H, H, H, 0, 0, 0, 1.f, 0, nullptr, 1);
    }
    rope_kernel<<<S, 1024>>>(positions, q, k);

    // --- fused flash attention (v2) ---
    flash_attn_kernel<<<dim3(S / 64, NH), 128, FA_TOT * 4>>>(q, k, v, attn);

    // --- O proj (split-K 2, residual fused into reduce) ---
    {
        GSets s{}; s.s[0] = {o_w, nullptr, nullptr};
        long long sSplit = (long long)S * H;
        gemm_multi(attn, s, 1, S, H, H, H, H, 0, 0, 0, 0,
                   1.f, 0, nullptr, 1, 2, 1024, part, sSplit);
        reduce_split_kernel<<<(S * H / 4 + 255) / 256, 256>>>(
            (const float4*)part, (float4*)x2, (const float4*)hidden,
            2, (long long)S * H / 4, (long long)S * H / 4);
    }

    rmsnorm_kernel<<<S, 256>>>(x2, ln2, h2);

    // --- shared expert ---
    {
        GSets s{};
        s.s[0] = {ws_gate, gs, nullptr};
        s.s[1] = {ws_up,   us, nullptr};
        gemm_multi(h2, s, 2, S, IS, H, H, IS, IS, 0, 0, 0, 1.f, 0, nullptr, 1);
    }
    silumul4_kernel<<<(S * IS / 4 + 255) / 256, 256>>>((float4*)gs, (const float4*)us, S * IS / 4);
    {
        GSets s{}; s.s[0] = {ws_down, nullptr, nullptr};
        long long sSplit = (long long)S * H;
        gemm_multi(gs, s, 1, S, H, IS, IS, H, 0, 0, 0, 0,
                   1.f, 0, nullptr, 1, 2, 2816, part, sSplit);
        reduce_split_kernel<<<(S * H / 4 + 255) / 256, 256>>>(
            (const float4*)part, (float4*)shrd, nullptr,
            2, (long long)S * H / 4, (long long)S * H / 4);
    }
    sgate_kernel<<<S, 256>>>(h2, wsg, sgv);

    // --- router + dispatch (gather-free) ---
    gemm1(h2, router_w, nullptr, logits, S, E, H, H, E, E, 0, 0, 0, 1.f, 0, nullptr, 1);
    zero_cnt_kernel<<<1, 32>>>(cnt);
    routing_kernel<<<(S + 255) / 256, 256>>>(logits, cnt, tke, tks, tkw, tok);

    // --- expert MLPs ---
    {
        GSets s{};
        s.s[0] = {we_gate, gbuf, nullptr};
        s.s[1] = {we_up,   ubuf, nullptr};
        gemm_multi(h2, s, 2, S, IM, H, H, IM, IM,
                   0, (long long)H * IM, (long long)S * IM,
                   1.f, 0, cnt, E, 1, 0, nullptr, 0, tok);
    }
    silumul_expert_kernel<<<dim3(S, E), 256>>>((float4*)gbuf, (const float4*)ubuf, cnt);
    gemm1(gbuf, we_down, nullptr, ybuf, S, H, IM, IM, H, H,
          (long long)S * IM, (long long)IM * H, (long long)S * H, 1.f, 0, cnt, E);

    // --- final combine ---
    combine_kernel<<<S, 256>>>(shrd, sgv, ybuf, tke, tks, tkw, out);
}

// round 9
// speedup vs baseline: 1.3398x; 1.3398x over previous
#include <cuda_runtime.h>
#include <math.h>
#include <stdint.h>

#define S   1024
#define H   2048
#define NH  16
#define HD  128
#define E   16
#define TOPK 4
#define IM  1408
#define IS  5632
#define EPS 1e-6f

// ---------------- scratch (device globals) ----------------
__device__ float g_h1[S*H];
__device__ float g_q[S*H];
__device__ float g_k[S*H];
__device__ float g_v[S*H];
__device__ float g_attn[S*H];
__device__ float g_x2[S*H];
__device__ float g_h2[S*H];
__device__ float g_gs[S*IS];
__device__ float g_us[S*IS];
__device__ float g_shared[S*H];
__device__ float g_logits[S*E];
__device__ float g_sg[S];
__device__ int   g_cnt[E];
__device__ int   g_tk_e[S*TOPK];
__device__ int   g_tk_slot[S*TOPK];
__device__ float g_tk_w[S*TOPK];
__device__ int   g_tok[E*S];
__device__ float g_gbuf[E*S*IM];
__device__ float g_ubuf[E*S*IM];
__device__ float g_ybuf[E*S*H];
__device__ float g_part[12582912];   // split-K partials (50 MB): covers 3 sets x 2 splits x S*H

// ---------------- block reductions ----------------
__device__ __forceinline__ float blockReduceSum(float v) {
    __shared__ float sh[33];
    int lane = threadIdx.x & 31, wid = threadIdx.x >> 5;
    #pragma unroll
    for (int o = 16; o; o >>= 1) v += __shfl_down_sync(0xffffffffu, v, o);
    if (lane == 0) sh[wid] = v;
    __syncthreads();
    int nw = (blockDim.x + 31) >> 5;
    float t = (threadIdx.x < nw) ? sh[threadIdx.x] : 0.f;
    if (wid == 0) {
        #pragma unroll
        for (int o = 16; o; o >>= 1) t += __shfl_down_sync(0xffffffffu, t, o);
        if (lane == 0) sh[32] = t;
    }
    __syncthreads();
    float r = sh[32];
    __syncthreads();
    return r;
}

// ---------------- tf32 helpers ----------------
__device__ __forceinline__ uint32_t f2tf32(float f) {
    uint32_t r;
    asm("cvt.rna.tf32.f32 %0, %1;" : "=r"(r) : "f"(f));
    return r;
}

__device__ __forceinline__ void mma_tf32(float& d0, float& d1, float& d2, float& d3,
                                         uint32_t a0, uint32_t a1, uint32_t a2, uint32_t a3,
                                         uint32_t b0, uint32_t b1) {
    asm volatile(
        "mma.sync.aligned.m16n8k8.row.col.f32.tf32.tf32.f32 "
        "{%0,%1,%2,%3}, {%4,%5,%6,%7}, {%8,%9}, {%0,%1,%2,%3};"
        : "+f"(d0), "+f"(d1), "+f"(d2), "+f"(d3)
        : "r"(a0), "r"(a1), "r"(a2), "r"(a3), "r"(b0), "r"(b1));
}

__device__ __forceinline__ void cp_async16(uint32_t smem_addr, const void* gptr) {
    asm volatile("cp.async.cg.shared.global [%0], [%1], 16;"
                 :: "r"(smem_addr), "l"(gptr));
}
__device__ __forceinline__ void cp_commit() {
    asm volatile("cp.async.commit_group;" ::: "memory");
}
__device__ __forceinline__ void cp_wait0() {
    asm volatile("cp.async.wait_group 0;" ::: "memory");
}

// ---------------- TF32 GEMM: R7 config (BK=16, 128 threads, 64x64 warp tiles) ----------------
#define LDA_SH 20
#define LDB_SH 136
#define STG_SZ (128 * LDA_SH)

struct GSet { const float* B; float* C; const float* bias; };
struct GSets { GSet s[3]; };

__device__ __forceinline__ void stage_load(
    float4* avr, float4* bvr,
    const float* const* aRowP, const float* const* bRowP, const float* bCol,
    int kt, int ldb, int transB, int acq, int brow)
{
    const float4 zf4 = make_float4(0.f, 0.f, 0.f, 0.f);
    #pragma unroll
    for (int p = 0; p < 4; p++)
        avr[p] = aRowP[p] ? *reinterpret_cast<const float4*>(aRowP[p] + kt + acq) : zf4;
    if (!transB) {
        #pragma unroll
        for (int p = 0; p < 4; p++)
            bvr[p] = bCol ? *reinterpret_cast<const float4*>(bCol + (long long)(kt + brow + 4 * p) * ldb) : zf4;
    } else {
        #pragma unroll
        for (int p = 0; p < 4; p++)
            bvr[p] = bRowP[p] ? *reinterpret_cast<const float4*>(bRowP[p] + kt + acq) : zf4;
    }
}

__device__ __forceinline__ void stage_store(
    uint32_t* As, uint32_t* Bs, const float4* avr, const float4* bvr,
    int transB, int arow, int acq, int brow, int bn4)
{
    #pragma unroll
    for (int p = 0; p < 4; p++) {
        int r = arow + p * 32;
        uint4 v = make_uint4(f2tf32(avr[p].x), f2tf32(avr[p].y),
                             f2tf32(avr[p].z), f2tf32(avr[p].w));
        *reinterpret_cast<uint4*>(&As[r * LDA_SH + acq]) = v;
    }
    if (!transB) {
        #pragma unroll
        for (int p = 0; p < 4; p++) {
            int k = brow + p * 4;
            uint4 v = make_uint4(f2tf32(bvr[p].x), f2tf32(bvr[p].y),
                                 f2tf32(bvr[p].z), f2tf32(bvr[p].w));
            *reinterpret_cast<uint4*>(&Bs[k * LDB_SH + bn4]) = v;
        }
    } else {
        #pragma unroll
        for (int p = 0; p < 4; p++) {
            int r = arow + p * 32;
            uint4 v = make_uint4(f2tf32(bvr[p].x), f2tf32(bvr[p].y),
                                 f2tf32(bvr[p].z), f2tf32(bvr[p].w));
            *reinterpret_cast<uint4*>(&Bs[r * LDA_SH + acq]) = v;
        }
    }
}

// split-K partial layout: part + ((set*inner + ib)*nsplit + sp) * (Mfull*N)
__global__ void __launch_bounds__(128, 2)
tgemm_kernel(const float* __restrict__ A, GSets sets,
             int M, int N, int K, int lda, int ldb, int ldc,
             long long sA, long long sB, long long sC,
             float alpha, int transB, const int* __restrict__ mcnt,
             int inner, int nsplit, int ksz,
             float* __restrict__ part,
             const int* __restrict__ rowidx_all)
{
    const int z = blockIdx.z;
    const int sp  = z % nsplit;
    const int t   = z / nsplit;
    const int ib  = t % inner;
    const int set = t / inner;

    const int Mfull = M;
    if (mcnt) M = mcnt[ib];
    const int m0 = blockIdx.y * 128;
    if (m0 >= M) return;
    const int n0 = blockIdx.x * 128;

    const float* Ab = A + (long long)ib * sA;
    const float* Bb = sets.s[set].B + (long long)ib * sB;
    const float* bias = sets.s[set].bias;
    const int* rowidx = rowidx_all ? rowidx_all + (long long)ib * S : nullptr;
    float* Cb;
    int ldcc;
    if (nsplit > 1) {
        Cb = part + (((long long)set * inner + ib) * nsplit + sp) * ((long long)Mfull * N);
        ldcc = N;
        bias = nullptr;
    } else {
        Cb = sets.s[set].C + (long long)ib * sC;
        ldcc = ldc;
    }

    const int kbeg = (nsplit > 1) ? sp * ksz : 0;
    const int kend = (nsplit > 1) ? kbeg + ksz : K;

    __shared__ uint32_t As[2][STG_SZ];
    __shared__ uint32_t Bs[2][STG_SZ];

    const int tid  = threadIdx.x;
    const int lane = tid & 31;
    const int warp = tid >> 5;          // 0..3
    const int wm   = (warp & 1) * 64;   // 2x2 warp grid, 64x64 tiles
    const int wn   = (warp >> 1) * 64;
    const int g    = lane >> 2;
    const int tg   = lane & 3;

    const int arow = tid >> 2;          // 0..31 (+32p)
    const int acq  = (tid & 3) * 4;
    const int brow = tid >> 5;          // 0..3  (+4p)
    const int bn4  = (tid & 31) * 4;

    const float* aRowP[4];
    #pragma unroll
    for (int p = 0; p < 4; p++) {
        int r = m0 + arow + p * 32;
        if (r < M) {
            long long gr = rowidx ? (long long)rowidx[r] : (long long)r;
            aRowP[p] = Ab + gr * lda;
        } else aRowP[p] = nullptr;
    }
    const float* bRowP[4] = {nullptr, nullptr, nullptr, nullptr};
    const float* bCol = nullptr;
    if (!transB) {
        if (n0 + bn4 < N) bCol = Bb + n0 + bn4;
    } else {
        #pragma unroll
        for (int p = 0; p < 4; p++) {
            int r = n0 + arow + p * 32;
            if (r < N) bRowP[p] = Bb + (long long)r * ldb;
        }
    }

    float acc[4][8][4];
    #pragma unroll
    for (int i = 0; i < 4; i++)
        #pragma unroll
        for (int j = 0; j < 8; j++)
            #pragma unroll
            for (int c = 0; c < 4; c++) acc[i][j][c] = 0.f;

    float4 avr[4], bvr[4];

    stage_load(avr, bvr, aRowP, bRowP, bCol, kbeg, ldb, transB, acq, brow);
    stage_store(As[0], Bs[0], avr, bvr, transB, arow, acq, brow, bn4);
    __syncthreads();

    int p = 0;
    for (int kt = kbeg; kt < kend; kt += 16) {
        const bool has_next = (kt + 16 < kend);
        if (has_next)
            stage_load(avr, bvr, aRowP, bRowP, bCol, kt + 16, ldb, transB, acq, brow);

        const uint32_t* Asp = As[p];
        const uint32_t* Bsp = Bs[p];
        #pragma unroll
        for (int kk = 0; kk < 16; kk += 8) {
            uint32_t af[4][4];
            #pragma unroll
            for (int mt = 0; mt < 4; mt++) {
                const uint32_t* base = &Asp[(wm + mt * 16 + g) * LDA_SH + kk + tg];
                af[mt][0] = base[0];
                af[mt][1] = base[8 * LDA_SH];
                af[mt][2] = base[4];
                af[mt][3] = base[8 * LDA_SH + 4];
            }
            uint32_t bf[8][2];
            if (!transB) {
                #pragma unroll
                for (int nt = 0; nt < 8; nt++) {
                    int n = wn + nt * 8 + g;
                    bf[nt][0] = Bsp[(kk + tg) * LDB_SH + n];
                    bf[nt][1] = Bsp[(kk + tg + 4) * LDB_SH + n];
                }
            } else {
                #pragma unroll
                for (int nt = 0; nt < 8; nt++) {
                    int n = wn + nt * 8 + g;
                    bf[nt][0] = Bsp[n * LDA_SH + kk + tg];
                    bf[nt][1] = Bsp[n * LDA_SH + kk + tg + 4];
                }
            }
            #pragma unroll
            for (int mt = 0; mt < 4; mt++)
                #pragma unroll
                for (int nt = 0; nt < 8; nt++)
                    mma_tf32(acc[mt][nt][0], acc[mt][nt][1], acc[mt][nt][2], acc[mt][nt][3],
                             af[mt][0], af[mt][1], af[mt][2], af[mt][3],
                             bf[nt][0], bf[nt][1]);
        }

        if (has_next) {
            stage_store(As[1 - p], Bs[1 - p], avr, bvr, transB, arow, acq, brow, bn4);
            __syncthreads();
            p ^= 1;
        }
    }

    #pragma unroll
    for (int mt = 0; mt < 4; mt++) {
        int r0 = m0 + wm + mt * 16 + g;
        int r1 = r0 + 8;
        #pragma unroll
        for (int nt = 0; nt < 8; nt++) {
            int col = n0 + wn + nt * 8 + 2 * tg;
            if (col >= N) continue;
            float b0 = bias ? bias[col]     : 0.f;
            float b1 = bias ? bias[col + 1] : 0.f;
            if (r0 < M) {
                float2 v = make_float2(acc[mt][nt][0] * alpha + b0,
                                       acc[mt][nt][1] * alpha + b1);
                *reinterpret_cast<float2*>(&Cb[(long long)r0 * ldcc + col]) = v;
            }
            if (r1 < M) {
                float2 v = make_float2(acc[mt][nt][2] * alpha + b0,
                                       acc[mt][nt][3] * alpha + b1);
                *reinterpret_cast<float2*>(&Cb[(long long)r1 * ldcc + col]) = v;
            }
        }
    }
}

// linear float4 split-K reduce (single set): C = sum_sp P + (addend?)
__global__ void reduce_split_kernel(const float4* __restrict__ P, float4* __restrict__ C,
                                    const float4* __restrict__ addend,
                                    int nsplit, long long sSplit4, long long total4)
{
    long long i = (long long)blockIdx.x * blockDim.x + threadIdx.x;
    if (i >= total4) return;
    float4 s = P[i];
    for (int sp = 1; sp < nsplit; sp++) {
        float4 t = P[sp * sSplit4 + i];
        s.x += t.x; s.y += t.y; s.z += t.z; s.w += t.w;
    }
    if (addend) {
        float4 t = addend[i];
        s.x += t.x; s.y += t.y; s.z += t.z; s.w += t.w;
    }
    C[i] = s;
}

// QKV split-K reduce: 3 sets x 2 splits, per-set bias, writes q/k/v
struct OutSet { float* C; const float* bias; };
__global__ void reduce_qkv_kernel(const float4* __restrict__ P,
                                  OutSet o0, OutSet o1, OutSet o2)
{
    const long long SH4 = (long long)S * H / 4;
    int set = blockIdx.y;
    OutSet o = (set == 0) ? o0 : (set == 1) ? o1 : o2;
    const float4* bias4 = reinterpret_cast<const float4*>(o.bias);
    float4* C = reinterpret_cast<float4*>(o.C);
    for (long long i = (long long)blockIdx.x * blockDim.x + threadIdx.x; i < SH4;
         i += (long long)gridDim.x * blockDim.x) {
        float4 a = P[(set * 2 + 0) * SH4 + i];
        float4 b = P[(set * 2 + 1) * SH4 + i];
        float4 bb = bias4[i & (H / 4 - 1)];
        C[i] = make_float4(a.x + b.x + bb.x, a.y + b.y + bb.y,
                           a.z + b.z + bb.z, a.w + b.w + bb.w);
    }
}

// ---------------- flash attention v2 (unchanged) ----------------
#define FAQ_LD 132
#define FAK_LD 132
#define FAV_LD 136
#define FAP_LD 36
#define FA_QS   0
#define FA_KV0  (64*FAQ_LD)
#define FA_KVST (32*FAK_LD + 32*FAV_LD)
#define FA_PS   (FA_KV0 + 2*FA_KVST)
#define FA_TOT  (FA_PS + 4*16*FAP_LD)
#define ATTN_SCALE 0.08838834764831845f

__global__ void __launch_bounds__(128)
flash_attn_kernel(const float* __restrict__ Q, const float* __restrict__ K,
                  const float* __restrict__ V, float* __restrict__ O)
{
    extern __shared__ uint32_t sh[];
    const int qb   = (gridDim.x - 1) - blockIdx.x;
    const int hh   = blockIdx.y;
    const int tid  = threadIdx.x;
    const int lane = tid & 31;
    const int warp = tid >> 5;
    const int g    = lane >> 2;
    const int tg   = lane & 3;
    const int wm   = warp * 16;
    const int q0   = qb * 64;
    const long long hoff = (long long)hh * HD;

    const uint32_t shbase = (uint32_t)__cvta_generic_to_shared(sh);

    #pragma unroll
    for (int j = 0; j < 16; j++) {
        int idx = tid + 128 * j;
        int r = idx >> 5, c4 = (idx & 31) * 4;
        float4 t = *reinterpret_cast<const float4*>(&Q[(long long)(q0 + r) * H + hoff + c4]);
        uint4 v = make_uint4(f2tf32(t.x * ATTN_SCALE), f2tf32(t.y * ATTN_SCALE),
                             f2tf32(t.z * ATTN_SCALE), f2tf32(t.w * ATTN_SCALE));
        *reinterpret_cast<uint4*>(&sh[FA_QS + r * FAQ_LD + c4]) = v;
    }

    const int ldrow = tid >> 5;
    const int ldc4  = (tid & 31) * 4;

    auto issue_chunk = [&](int c, int s) {
        uint32_t kbase = shbase + (FA_KV0 + s * FA_KVST) * 4;
        uint32_t vbase = kbase + 32 * FAK_LD * 4;
        #pragma unroll
        for (int j = 0; j < 8; j++) {
            int r = ldrow + 4 * j;
            long long gofs = (long long)(c * 32 + r) * H + hoff + ldc4;
            cp_async16(kbase + (r * FAK_LD + ldc4) * 4, &K[gofs]);
            cp_async16(vbase + (r * FAV_LD + ldc4) * 4, &V[gofs]);
        }
        cp_commit();
    };

    float Oacc[16][4];
    #pragma unroll
    for (int nt = 0; nt < 16; nt++)
        #pragma unroll
        for (int c = 0; c < 4; c++) Oacc[nt][c] = 0.f;
    float m0r = -1e30f, m1r = -1e30f, l0r = 0.f, l1r = 0.f;

    uint32_t* Pw = &sh[FA_PS + warp * 16 * FAP_LD];
    const int nc = 2 * qb + 2;

    issue_chunk(0, 0);

    for (int c = 0; c < nc; c++) {
        cp_wait0();
        __syncthreads();
        if (c + 1 < nc) issue_chunk(c + 1, (c + 1) & 1);

        const uint32_t* K_ = &sh[FA_KV0 + (c & 1) * FA_KVST];
        const uint32_t* V_ = K_ + 32 * FAK_LD;

        float Sacc[4][4];
        #pragma unroll
        for (int nt = 0; nt < 4; nt++)
            #pragma unroll
            for (int cc = 0; cc < 4; cc++) Sacc[nt][cc] = 0.f;

        #pragma unroll
        for (int kk = 0; kk < 128; kk += 8) {
            uint32_t a0 = sh[FA_QS + (wm + g) * FAQ_LD + kk + tg];
            uint32_t a1 = sh[FA_QS + (wm + g + 8) * FAQ_LD + kk + tg];
            uint32_t a2 = sh[FA_QS + (wm + g) * FAQ_LD + kk + tg + 4];
            uint32_t a3 = sh[FA_QS + (wm + g + 8) * FAQ_LD + kk + tg + 4];
            #pragma unroll
            for (int nt = 0; nt < 4; nt++) {
                uint32_t b0 = K_[(nt * 8 + g) * FAK_LD + kk + tg];
                uint32_t b1 = K_[(nt * 8 + g) * FAK_LD + kk + tg + 4];
                mma_tf32(Sacc[nt][0], Sacc[nt][1], Sacc[nt][2], Sacc[nt][3],
                         a0, a1, a2, a3, b0, b1);
            }
        }

        if (c >= 2 * qb) {
            int r0g = q0 + wm + g, r1g = r0g + 8;
            #pragma unroll
            for (int nt = 0; nt < 4; nt++) {
                int c0 = c * 32 + nt * 8 + 2 * tg, c1 = c0 + 1;
                if (c0 > r0g) Sacc[nt][0] = -1e30f;
                if (c1 > r0g) Sacc[nt][1] = -1e30f;
                if (c0 > r1g) Sacc[nt][2] = -1e30f;
                if (c1 > r1g) Sacc[nt][3] = -1e30f;
            }
        }

        float rmax0 = -1e30f, rmax1 = -1e30f;
        #pragma unroll
        for (int nt = 0; nt < 4; nt++) {
            rmax0 = fmaxf(rmax0, fmaxf(Sacc[nt][0], Sacc[nt][1]));
            rmax1 = fmaxf(rmax1, fmaxf(Sacc[nt][2], Sacc[nt][3]));
        }
        rmax0 = fmaxf(rmax0, __shfl_xor_sync(0xffffffffu, rmax0, 1));
        rmax0 = fmaxf(rmax0, __shfl_xor_sync(0xffffffffu, rmax0, 2));
        rmax1 = fmaxf(rmax1, __shfl_xor_sync(0xffffffffu, rmax1, 1));
        rmax1 = fmaxf(rmax1, __shfl_xor_sync(0xffffffffu, rmax1, 2));

        float nm0 = fmaxf(m0r, rmax0), nm1 = fmaxf(m1r, rmax1);
        float al0 = __expf(m0r - nm0), al1 = __expf(m1r - nm1);
        float sum0 = 0.f, sum1 = 0.f;
        #pragma unroll
        for (int nt = 0; nt < 4; nt++) {
            float p00 = __expf(Sacc[nt][0] - nm0);
            float p01 = __expf(Sacc[nt][1] - nm0);
            float p10 = __expf(Sacc[nt][2] - nm1);
            float p11 = __expf(Sacc[nt][3] - nm1);
            sum0 += p00 + p01; sum1 += p10 + p11;
            int cl = nt * 8 + 2 * tg;
            Pw[g * FAP_LD + cl]           = f2tf32(p00);
            Pw[g * FAP_LD + cl + 1]       = f2tf32(p01);
            Pw[(g + 8) * FAP_LD + cl]     = f2tf32(p10);
            Pw[(g + 8) * FAP_LD + cl + 1] = f2tf32(p11);
        }
        sum0 += __shfl_xor_sync(0xffffffffu, sum0, 1);
        sum0 += __shfl_xor_sync(0xffffffffu, sum0, 2);
        sum1 += __shfl_xor_sync(0xffffffffu, sum1, 1);
        sum1 += __shfl_xor_sync(0xffffffffu, sum1, 2);
        l0r = l0r * al0 + sum0;
        l1r = l1r * al1 + sum1;
        m0r = nm0; m1r = nm1;

        #pragma unroll
        for (int nt = 0; nt < 16; nt++) {
            Oacc[nt][0] *= al0; Oacc[nt][1] *= al0;
            Oacc[nt][2] *= al1; Oacc[nt][3] *= al1;
        }

        __syncwarp();

        #pragma unroll
        for (int kk = 0; kk < 32; kk += 8) {
            uint32_t a0 = Pw[g * FAP_LD + kk + tg];
            uint32_t a1 = Pw[(g + 8) * FAP_LD + kk + tg];
            uint32_t a2 = Pw[g * FAP_LD + kk + tg + 4];
            uint32_t a3 = Pw[(g + 8) * FAP_LD + kk + tg + 4];
            #pragma unroll
            for (int nt = 0; nt < 16; nt++) {
                uint32_t b0 = V_[(kk + tg) * FAV_LD + nt * 8 + g];
                uint32_t b1 = V_[(kk + tg + 4) * FAV_LD + nt * 8 + g];
                mma_tf32(Oacc[nt][0], Oacc[nt][1], Oacc[nt][2], Oacc[nt][3],
                         a0, a1, a2, a3, b0, b1);
            }
        }
    }

    float inv0 = 1.f / l0r, inv1 = 1.f / l1r;
    long long r0 = q0 + wm + g, r1 = r0 + 8;
    #pragma unroll
    for (int nt = 0; nt < 16; nt++) {
        int c = nt * 8 + 2 * tg;
        *reinterpret_cast<float2*>(&O[r0 * H + hoff + c]) =
            make_float2(Oacc[nt][0] * inv0, Oacc[nt][1] * inv0);
        *reinterpret_cast<float2*>(&O[r1 * H + hoff + c]) =
            make_float2(Oacc[nt][2] * inv1, Oacc[nt][3] * inv1);
    }
}

// ---------------- elementwise / norm ----------------
__global__ void rmsnorm_kernel(const float* __restrict__ x, const float* __restrict__ w,
                               float* __restrict__ y) {
    int t = blockIdx.x;
    const float4* xr = reinterpret_cast<const float4*>(x + (long long)t * H);
    const float4* w4 = reinterpret_cast<const float4*>(w);
    float4* yr = reinterpret_cast<float4*>(y + (long long)t * H);
    float s = 0.f;
    for (int i = threadIdx.x; i < H / 4; i += blockDim.x) {
        float4 v = xr[i];
        s += v.x * v.x + v.y * v.y + v.z * v.z + v.w * v.w;
    }
    s = blockReduceSum(s);
    float scale = rsqrtf(s / (float)H + EPS);
    for (int i = threadIdx.x; i < H / 4; i += blockDim.x) {
        float4 v = xr[i], ww = w4[i];
        yr[i] = make_float4(v.x * scale * ww.x, v.y * scale * ww.y,
                            v.z * scale * ww.z, v.w * scale * ww.w);
    }
}

__global__ void rope_kernel(const int* __restrict__ pos, float* __restrict__ q,
                            float* __restrict__ k) {
    int t = blockIdx.x;
    int h = threadIdx.x >> 6;
    int d = threadIdx.x & 63;
    float p = (float)pos[t];
    float inv = exp2f(-(float)d * 0.31143075889569023f);
    float ang = p * inv;
    float sn, cs;
    sincosf(ang, &sn, &cs);
    long long base = (long long)t * H + h * HD;
    float x1 = q[base + d], x2 = q[base + 64 + d];
    q[base + d]      = x1 * cs - x2 * sn;
    q[base + 64 + d] = x2 * cs + x1 * sn;
    x1 = k[base + d]; x2 = k[base + 64 + d];
    k[base + d]      = x1 * cs - x2 * sn;
    k[base + 64 + d] = x2 * cs + x1 * sn;
}

__global__ void silumul4_kernel(float4* __restrict__ g, const float4* __restrict__ u, int n4) {
    int i = blockIdx.x * blockDim.x + threadIdx.x;
    if (i >= n4) return;
    float4 x = g[i], y = u[i];
    x.x = (x.x / (1.f + __expf(-x.x))) * y.x;
    x.y = (x.y / (1.f + __expf(-x.y))) * y.y;
    x.z = (x.z / (1.f + __expf(-x.z))) * y.z;
    x.w = (x.w / (1.f + __expf(-x.w))) * y.w;
    g[i] = x;
}

__global__ void sgate_kernel(const float* __restrict__ h2, const float* __restrict__ wsg,
                             float* __restrict__ sg) {
    int t = blockIdx.x;
    const float4* xr = reinterpret_cast<const float4*>(h2 + (long long)t * H);
    const float4* w4 = reinterpret_cast<const float4*>(wsg);
    float s = 0.f;
    for (int i = threadIdx.x; i < H / 4; i += blockDim.x) {
        float4 v = xr[i], w = w4[i];
        s += v.x * w.x + v.y * w.y + v.z * w.z + v.w * w.w;
    }
    s = blockReduceSum(s);
    if (threadIdx.x == 0) sg[t] = 1.f / (1.f + __expf(-s));
}

// ---------------- MoE routing ----------------
__global__ void zero_cnt_kernel(int* cnt) { if (threadIdx.x < E) cnt[threadIdx.x] = 0; }

__global__ void routing_kernel(const float* __restrict__ logits, int* __restrict__ cnt,
                               int* __restrict__ tke, int* __restrict__ tks,
                               float* __restrict__ tkw, int* __restrict__ tok) {
    int t = blockIdx.x * blockDim.x + threadIdx.x;
    if (t >= S) return;
    float p[E];
    float mx = -3.4e38f;
    #pragma unroll
    for (int e = 0; e < E; e++) { p[e] = logits[t * E + e]; mx = fmaxf(mx, p[e]); }
    float sum = 0.f;
    #pragma unroll
    for (int e = 0; e < E; e++) { p[e] = __expf(p[e] - mx); sum += p[e]; }
    float inv = 1.f / sum;
    #pragma unroll
    for (int e = 0; e < E; e++) p[e] *= inv;
    int ids[TOPK]; float ws[TOPK]; float wsum = 0.f;
    #pragma unroll
    for (int k = 0; k < TOPK; k++) {
        float bv = -1.f; int bi = 0;
        #pragma unroll
        for (int e = 0; e < E; e++) if (p[e] > bv) { bv = p[e]; bi = e; }
        ids[k] = bi; ws[k] = bv; wsum += bv; p[bi] = -2.f;
    }
    float wi = 1.f / wsum;
    #pragma unroll
    for (int k = 0; k < TOPK; k++) {
        int slot = atomicAdd(&cnt[ids[k]], 1);
        tke[t * TOPK + k] = ids[k];
        tks[t * TOPK + k] = slot;
        tkw[t * TOPK + k] = ws[k] * wi;
        tok[ids[k] * S + slot] = t;
    }
}

__global__ void silumul_expert_kernel(float4* __restrict__ gbuf, const float4* __restrict__ ubuf,
                                      const int* __restrict__ cnt) {
    int e = blockIdx.y, slot = blockIdx.x;
    if (slot >= cnt[e]) return;
    long long base = ((long long)e * S + slot) * (IM / 4);
    for (int i = threadIdx.x; i < IM / 4; i += blockDim.x) {
        float4 x = gbuf[base + i], y = ubuf[base + i];
        x.x = (x.x / (1.f + __expf(-x.x))) * y.x;
        x.y = (x.y / (1.f + __expf(-x.y))) * y.y;
        x.z = (x.z / (1.f + __expf(-x.z))) * y.z;
        x.w = (x.w / (1.f + __expf(-x.w))) * y.w;
        gbuf[base + i] = x;
    }
}

__global__ void combine_kernel(const float* __restrict__ shrd, const float* __restrict__ sg,
                               const float* __restrict__ ybuf,
                               const int* __restrict__ tke, const int* __restrict__ tks,
                               const float* __restrict__ tkw, float* __restrict__ out) {
    int t = blockIdx.x;
    float gg = sg[t];
    int e0 = tke[t*4+0], e1 = tke[t*4+1], e2 = tke[t*4+2], e3 = tke[t*4+3];
    int s0 = tks[t*4+0], s1 = tks[t*4+1], s2 = tks[t*4+2], s3 = tks[t*4+3];
    float w0 = tkw[t*4+0], w1 = tkw[t*4+1], w2 = tkw[t*4+2], w3 = tkw[t*4+3];
    const float4* y0 = reinterpret_cast<const float4*>(ybuf + ((long long)e0 * S + s0) * H);
    const float4* y1 = reinterpret_cast<const float4*>(ybuf + ((long long)e1 * S + s1) * H);
    const float4* y2 = reinterpret_cast<const float4*>(ybuf + ((long long)e2 * S + s2) * H);
    const float4* y3 = reinterpret_cast<const float4*>(ybuf + ((long long)e3 * S + s3) * H);
    const float4* sh4 = reinterpret_cast<const float4*>(shrd + (long long)t * H);
    float4* o = reinterpret_cast<float4*>(out + (long long)t * H);
    for (int i = threadIdx.x; i < H / 4; i += blockDim.x) {
        float4 a = sh4[i], b0 = y0[i], b1 = y1[i], b2 = y2[i], b3 = y3[i];
        o[i] = make_float4(
            gg * a.x + w0 * b0.x + w1 * b1.x + w2 * b2.x + w3 * b3.x,
            gg * a.y + w0 * b0.y + w1 * b1.y + w2 * b2.y + w3 * b3.y,
            gg * a.z + w0 * b0.z + w1 * b1.z + w2 * b2.z + w3 * b3.z,
            gg * a.w + w0 * b0.w + w1 * b1.w + w2 * b2.w + w3 * b3.w);
    }
}

// ---------------- host orchestration ----------------
static inline void gemm_multi(const float* A, const GSets& sets, int nsets,
                              int M, int N, int K, int lda, int ldb, int ldc,
                              long long sA, long long sB, long long sC,
                              float alpha, int transB, const int* mcnt, int inner,
                              int nsplit = 1, int ksz = 0, float* part = nullptr,
                              const int* rowidx = nullptr) {
    dim3 grid((N + 127) / 128, (M + 127) / 128, nsets * inner * nsplit);
    tgemm_kernel<<<grid, 128>>>(A, sets, M, N, K, lda, ldb, ldc, sA, sB, sC,
                                alpha, transB, mcnt, inner, nsplit, ksz, part, rowidx);
}

static inline void gemm1(const float* A, const float* B, const float* bias, float* C,
                         int M, int N, int K, int lda, int ldb, int ldc,
                         long long sA, long long sB, long long sC,
                         float alpha, int transB, const int* mcnt, int inner) {
    GSets s{}; s.s[0] = {B, C, bias};
    gemm_multi(A, s, 1, M, N, K, lda, ldb, ldc, sA, sB, sC, alpha, transB, mcnt, inner);
}

extern "C" void kernel_launch(void* const* d_in, const int* in_sizes, int n_in,
                              void* d_out, int out_size) {
    const int*   positions = (const int*)  d_in[0];
    const float* hidden    = (const float*)d_in[1];
    const float* ln1       = (const float*)d_in[2];
    const float* ln2       = (const float*)d_in[3];
    const float* q_w       = (const float*)d_in[4];
    const float* q_b       = (const float*)d_in[5];
    const float* k_w       = (const float*)d_in[6];
    const float* k_b       = (const float*)d_in[7];
    const float* v_w       = (const float*)d_in[8];
    const float* v_b       = (const float*)d_in[9];
    const float* o_w       = (const float*)d_in[10];
    const float* router_w  = (const float*)d_in[11];
    const float* we_gate   = (const float*)d_in[12];
    const float* we_up     = (const float*)d_in[13];
    const float* we_down   = (const float*)d_in[14];
    const float* ws_gate   = (const float*)d_in[15];
    const float* ws_up     = (const float*)d_in[16];
    const float* ws_down   = (const float*)d_in[17];
    const float* wsg       = (const float*)d_in[18];
    float* out = (float*)d_out;

    float *h1, *q, *k, *v, *attn, *x2, *h2, *gs, *us, *shrd;
    float *logits, *sgv, *gbuf, *ubuf, *ybuf, *tkw, *part;
    int *cnt, *tke, *tks, *tok;
    cudaGetSymbolAddress((void**)&h1,     g_h1);
    cudaGetSymbolAddress((void**)&q,      g_q);
    cudaGetSymbolAddress((void**)&k,      g_k);
    cudaGetSymbolAddress((void**)&v,      g_v);
    cudaGetSymbolAddress((void**)&attn,   g_attn);
    cudaGetSymbolAddress((void**)&x2,     g_x2);
    cudaGetSymbolAddress((void**)&h2,     g_h2);
    cudaGetSymbolAddress((void**)&gs,     g_gs);
    cudaGetSymbolAddress((void**)&us,     g_us);
    cudaGetSymbolAddress((void**)&shrd,   g_shared);
    cudaGetSymbolAddress((void**)&logits, g_logits);
    cudaGetSymbolAddress((void**)&sgv,    g_sg);
    cudaGetSymbolAddress((void**)&cnt,    g_cnt);
    cudaGetSymbolAddress((void**)&tke,    g_tk_e);
    cudaGetSymbolAddress((void**)&tks,    g_tk_slot);
    cudaGetSymbolAddress((void**)&tkw,    g_tk_w);
    cudaGetSymbolAddress((void**)&tok,    g_tok);
    cudaGetSymbolAddress((void**)&gbuf,   g_gbuf);
    cudaGetSymbolAddress((void**)&ubuf,   g_ubuf);
    cudaGetSymbolAddress((void**)&ybuf,   g_ybuf);
    cudaGetSymbolAddress((void**)&part,   g_part);

    cudaFuncSetAttribute(flash_attn_kernel,
                         cudaFuncAttributeMaxDynamicSharedMemorySize, FA_TOT * 4);

    // --- pre-attention norm + fused QKV (split-K 2) + RoPE ---
    rmsnorm_kernel<<<S, 256>>>(hidden, ln1, h1);
    {
        GSets s{};
        s.s[0] = {q_w, nullptr, nullptr};
        s.s[1] = {k_w, nullptr, nullptr};
        s.s[2] = {v_w, nullptr, nullptr};
        gemm_multi(h1, s, 3, S, H, H, H, H, H, 0, 0, 0, 1.f, 0, nullptr, 1,
                   2, 1024, part);
        OutSet oq{q, q_b}, ok{k, k_b}, ov{v, v_b};
        reduce_qkv_kernel<<<dim3(512, 3), 256>>>((const float4*)part, oq, ok, ov);
    }
    rope_kernel<<<S, 1024>>>(positions, q, k);

    // --- fused flash attention (v2) ---
    flash_attn_kernel<<<dim3(S / 64, NH), 128, FA_TOT * 4>>>(q, k, v, attn);

    // --- O proj (split-K 2, residual fused into reduce) ---
    {
        GSets s{}; s.s[0] = {o_w, nullptr, nullptr};
        gemm_multi(attn, s, 1, S, H, H, H, H, 0, 0, 0, 0,
                   1.f, 0, nullptr, 1, 2, 1024, part);
        reduce_split_kernel<<<(S * H / 4 + 255) / 256, 256>>>(
            (const float4*)part, (float4*)x2, (const float4*)hidden,
            2, (long long)S * H / 4, (long long)S * H / 4);
    }

    rmsnorm_kernel<<<S, 256>>>(x2, ln2, h2);

    // --- shared expert ---
    {
        GSets s{};
        s.s[0] = {ws_gate, gs, nullptr};
        s.s[1] = {ws_up,   us, nullptr};
        gemm_multi(h2, s, 2, S, IS, H, H, IS, IS, 0, 0, 0, 1.f, 0, nullptr, 1);
    }
    silumul4_kernel<<<(S * IS / 4 + 255) / 256, 256>>>((float4*)gs, (const float4*)us, S * IS / 4);
    {
        GSets s{}; s.s[0] = {ws_down, nullptr, nullptr};
        gemm_multi(gs, s, 1, S, H, IS, IS, H, 0, 0, 0, 0,
                   1.f, 0, nullptr, 1, 2, 2816, part);
        reduce_split_kernel<<<(S * H / 4 + 255) / 256, 256>>>(
            (const float4*)part, (float4*)shrd, nullptr,
            2, (long long)S * H / 4, (long long)S * H / 4);
    }
    sgate_kernel<<<S, 256>>>(h2, wsg, sgv);

    // --- router + dispatch (gather-free) ---
    gemm1(h2, router_w, nullptr, logits, S, E, H, H, E, E, 0, 0, 0, 1.f, 0, nullptr, 1);
    zero_cnt_kernel<<<1, 32>>>(cnt);
    routing_kernel<<<(S + 255) / 256, 256>>>(logits, cnt, tke, tks, tkw, tok);

    // --- expert MLPs ---
    {
        GSets s{};
        s.s[0] = {we_gate, gbuf, nullptr};
        s.s[1] = {we_up,   ubuf, nullptr};
        gemm_multi(h2, s, 2, S, IM, H, H, IM, IM,
                   0, (long long)H * IM, (long long)S * IM,
                   1.f, 0, cnt, E, 1, 0, nullptr, tok);
    }
    silumul_expert_kernel<<<dim3(S, E), 256>>>((float4*)gbuf, (const float4*)ubuf, cnt);
    gemm1(gbuf, we_down, nullptr, ybuf, S, H, IM, IM, H, H,
          (long long)S * IM, (long long)IM * H, (long long)S * H, 1.f, 0, cnt, E);

    // --- final combine ---
    combine_kernel<<<S, 256>>>(shrd, sgv, ybuf, tke, tks, tkw, out);
}